// round 7
// baseline (speedup 1.0000x reference)
#include <cuda_runtime.h>
#include <cuda_bf16.h>
#include <cstdint>
#include <math.h>

#define B_ROWS 8192
#define F_DIM  2048
#define F2_DIM 4096
#define DB 512
#define DA 256
#define DE 256
#define DM 512
#define DS 512

// ---- device scratch (allocation forbidden) ----
__device__ __align__(256) __nv_bfloat16 g_comb_hi[B_ROWS * F_DIM];
__device__ __align__(256) __nv_bfloat16 g_comb_lo[B_ROWS * F_DIM];
__device__ __align__(256) __nv_bfloat16 g_act_hi [B_ROWS * F2_DIM];
__device__ __align__(256) __nv_bfloat16 g_act_lo [B_ROWS * F2_DIM];
__device__ __align__(256) float g_f32a [B_ROWS * F_DIM];
__device__ __align__(256) float g_f32b [B_ROWS * F_DIM];
__device__ __align__(256) float g_fused[B_ROWS * F_DIM];
__device__ __align__(256) __nv_bfloat16 g_wk[4 * F_DIM * F_DIM];
__device__ __align__(256) __nv_bfloat16 g_w1h[F2_DIM * F_DIM];
__device__ __align__(256) __nv_bfloat16 g_w1l[F2_DIM * F_DIM];
__device__ __align__(256) __nv_bfloat16 g_w2h[F_DIM * F2_DIM];
__device__ __align__(256) __nv_bfloat16 g_w2l[F_DIM * F2_DIM];
__device__ float g_partials[4 * 64];
__device__ float g_scale[4];

// ---- helpers (baseline PTX only: cp.async, ldmatrix, mma.sync) ----
__device__ __forceinline__ uint32_t smem_u32(const void* p) {
    uint32_t a;
    asm("{ .reg .u64 t; cvta.to.shared.u64 t, %1; cvt.u32.u64 %0, t; }" : "=r"(a) : "l"(p));
    return a;
}
__device__ __forceinline__ uint32_t sw128(uint32_t x) { return x ^ ((x >> 3) & 0x70); }

__device__ __forceinline__ void cp16(uint32_t dst, const void* src) {
    asm volatile("cp.async.cg.shared.global [%0], [%1], 16;\n" :: "r"(dst), "l"(src) : "memory");
}
__device__ __forceinline__ void cp_commit() { asm volatile("cp.async.commit_group;\n" ::: "memory"); }
template <int N> __device__ __forceinline__ void cp_wait() {
    asm volatile("cp.async.wait_group %0;\n" :: "n"(N) : "memory");
}
__device__ __forceinline__ void ldsm4(uint32_t* r, uint32_t a) {
    asm volatile("ldmatrix.sync.aligned.m8n8.x4.shared.b16 {%0,%1,%2,%3}, [%4];"
        : "=r"(r[0]), "=r"(r[1]), "=r"(r[2]), "=r"(r[3]) : "r"(a));
}
__device__ __forceinline__ void mma16816(float* c, const uint32_t* a, uint32_t b0, uint32_t b1) {
    asm volatile("mma.sync.aligned.m16n8k16.row.col.f32.bf16.bf16.f32 "
        "{%0,%1,%2,%3}, {%4,%5,%6,%7}, {%8,%9}, {%0,%1,%2,%3};"
        : "+f"(c[0]), "+f"(c[1]), "+f"(c[2]), "+f"(c[3])
        : "r"(a[0]), "r"(a[1]), "r"(a[2]), "r"(a[3]), "r"(b0), "r"(b1));
}
__device__ __forceinline__ float gelu_erf(float h) {
    return 0.5f * h * (1.0f + erff(h * 0.70710678f));
}
__device__ __forceinline__ uint32_t pack2(__nv_bfloat16 a, __nv_bfloat16 b) {
    __nv_bfloat162 v; v.x = a; v.y = b;
    return *reinterpret_cast<uint32_t*>(&v);
}

// ---- GEMM: C[M,N] = sum_s A_s[M,K] @ B_s[N,K]^T ----
#define TILE_M 128
#define TILE_N 128
#define TILE_K 64
#define STAGE_BYTES (TILE_M * 128 + TILE_N * 128)   // 32KB
#define STAGES 3
#define GEMM_SMEM_DYN (STAGES * STAGE_BYTES + 1024)

__device__ __forceinline__ void load_tiles(uint32_t sa, uint32_t sb,
        const __nv_bfloat16* A, const __nv_bfloat16* Bm,
        int m0, int n0, int k0, int K, int tid) {
    const char* ab = (const char*)(A + (size_t)m0 * K + k0);
    const char* bb = (const char*)(Bm + (size_t)n0 * K + k0);
    size_t rb = (size_t)K * 2;
#pragma unroll
    for (int i = 0; i < 4; i++) {
        int t = tid + i * 256, row = t >> 3, ch = t & 7;
        cp16(sa + sw128(row * 128 + ch * 16), ab + (size_t)row * rb + ch * 16);
    }
#pragma unroll
    for (int i = 0; i < 4; i++) {
        int t = tid + i * 256, row = t >> 3, ch = t & 7;
        cp16(sb + sw128(row * 128 + ch * 16), bb + (size_t)row * rb + ch * 16);
    }
}

template <int EPI>
__global__ void __launch_bounds__(256)
gemm_tc(const __nv_bfloat16* A0, const __nv_bfloat16* A1, const __nv_bfloat16* A2,
        const __nv_bfloat16* B0, const __nv_bfloat16* B1, const __nv_bfloat16* B2,
        int n_split, int N, int K,
        const float* scale_ptr, const float* __restrict__ bias,
        float* outF, __nv_bfloat16* outH, __nv_bfloat16* outL) {
    extern __shared__ char smem[];
    uint32_t sbase = (smem_u32(smem) + 1023) & ~1023u;
    int tid = threadIdx.x, wid = tid >> 5, lane = tid & 31;
    int n0 = blockIdx.x * TILE_N, m0 = blockIdx.y * TILE_M;
    int wm = wid & 1, wn = wid >> 1;
    const __nv_bfloat16* Al[3] = {A0, A1, A2};
    const __nv_bfloat16* Bl[3] = {B0, B1, B2};
    const int KT = K / TILE_K;
    const int iters = n_split * KT;

    for (int p = 0; p < 2 && p < iters; ++p) {
        int sp = p / KT, kk = (p % KT) * TILE_K;
        uint32_t st = sbase + p * STAGE_BYTES;
        load_tiles(st, st + TILE_M * 128, Al[sp], Bl[sp], m0, n0, kk, K, tid);
        cp_commit();
    }

    float acc[4][4][4];
#pragma unroll
    for (int i = 0; i < 4; i++)
#pragma unroll
        for (int j = 0; j < 4; j++)
#pragma unroll
            for (int k = 0; k < 4; k++) acc[i][j][k] = 0.f;

    int q = lane >> 3, r = lane & 7;
    int aRow = wm * 64 + r + (q & 1) * 8;     // + mi*16
    int aCol = (q >> 1) * 16;                  // + ks*32 (bytes)
    int bRow = wn * 32 + r + (q >> 1) * 8;     // + nj*16
    int bCol = (q & 1) * 16;

    for (int it = 0; it < iters; ++it) {
        cp_wait<1>();
        __syncthreads();
        if (it + 2 < iters) {
            int nit = it + 2, sp = nit / KT, kk = (nit % KT) * TILE_K;
            uint32_t st = sbase + (nit % STAGES) * STAGE_BYTES;
            load_tiles(st, st + TILE_M * 128, Al[sp], Bl[sp], m0, n0, kk, K, tid);
        }
        cp_commit();
        uint32_t sA = sbase + (it % STAGES) * STAGE_BYTES;
        uint32_t sB = sA + TILE_M * 128;
#pragma unroll
        for (int ks = 0; ks < 4; ++ks) {
            uint32_t a[4][4], b[2][4];
#pragma unroll
            for (int mi = 0; mi < 4; ++mi)
                ldsm4(a[mi], sA + sw128((aRow + mi * 16) * 128 + aCol + ks * 32));
#pragma unroll
            for (int nj = 0; nj < 2; ++nj)
                ldsm4(b[nj], sB + sw128((bRow + nj * 16) * 128 + bCol + ks * 32));
#pragma unroll
            for (int mi = 0; mi < 4; ++mi)
#pragma unroll
                for (int n8 = 0; n8 < 4; ++n8)
                    mma16816(acc[mi][n8], a[mi],
                             b[n8 >> 1][(n8 & 1) * 2], b[n8 >> 1][(n8 & 1) * 2 + 1]);
        }
    }

    float sc = scale_ptr ? *scale_ptr : 1.0f;
    int group = lane >> 2, tg = lane & 3;
#pragma unroll
    for (int mi = 0; mi < 4; ++mi) {
#pragma unroll
        for (int n8 = 0; n8 < 4; ++n8) {
            int row = m0 + wm * 64 + mi * 16 + group;
            int col = n0 + wn * 32 + n8 * 8 + tg * 2;
            float bb0 = bias[col], bb1 = bias[col + 1];
            float y0 = fmaf(sc, acc[mi][n8][0], bb0);
            float y1 = fmaf(sc, acc[mi][n8][1], bb1);
            float y2 = fmaf(sc, acc[mi][n8][2], bb0);
            float y3 = fmaf(sc, acc[mi][n8][3], bb1);
            if (EPI == 0) {
                y0 = gelu_erf(y0); y1 = gelu_erf(y1);
                y2 = gelu_erf(y2); y3 = gelu_erf(y3);
                __nv_bfloat16 h0 = __float2bfloat16(y0), h1 = __float2bfloat16(y1);
                __nv_bfloat16 h2 = __float2bfloat16(y2), h3 = __float2bfloat16(y3);
                *(uint32_t*)&outH[(size_t)row * N + col] = pack2(h0, h1);
                *(uint32_t*)&outH[(size_t)(row + 8) * N + col] = pack2(h2, h3);
                *(uint32_t*)&outL[(size_t)row * N + col] =
                    pack2(__float2bfloat16(y0 - __bfloat162float(h0)),
                          __float2bfloat16(y1 - __bfloat162float(h1)));
                *(uint32_t*)&outL[(size_t)(row + 8) * N + col] =
                    pack2(__float2bfloat16(y2 - __bfloat162float(h2)),
                          __float2bfloat16(y3 - __bfloat162float(h3)));
            } else {
                float2 v0 = make_float2(y0, y1), v1 = make_float2(y2, y3);
                *(float2*)&outF[(size_t)row * N + col] = v0;
                *(float2*)&outF[(size_t)(row + 8) * N + col] = v1;
            }
        }
    }
}

// ---- elementwise kernels ----
__device__ __forceinline__ float warpSum(float x) {
#pragma unroll
    for (int o = 16; o > 0; o >>= 1) x += __shfl_xor_sync(0xffffffffu, x, o);
    return x;
}

__global__ void absmean_partial(const float* w0, const float* w1, const float* w2, const float* w3) {
    const float* w = (blockIdx.y == 0) ? w0 : (blockIdx.y == 1) ? w1 : (blockIdx.y == 2) ? w2 : w3;
    const int chunk = (F_DIM * F_DIM) / 64;
    int base = blockIdx.x * chunk;
    float s = 0.f;
    for (int i = threadIdx.x; i < chunk; i += 256) s += fabsf(w[base + i]);
    __shared__ float red[8];
    s = warpSum(s);
    int wd = threadIdx.x >> 5, ln = threadIdx.x & 31;
    if (ln == 0) red[wd] = s;
    __syncthreads();
    if (wd == 0) {
        float v = (ln < 8) ? red[ln] : 0.f;
        v = warpSum(v);
        if (ln == 0) g_partials[blockIdx.y * 64 + blockIdx.x] = v;
    }
}

__global__ void quantize_ternary(const float* __restrict__ w, __nv_bfloat16* __restrict__ kq, int slot) {
    float sum = 0.f;
#pragma unroll
    for (int i = 0; i < 64; i++) sum += g_partials[slot * 64 + i];
    float s = sum * (1.0f / (float)(F_DIM * F_DIM));
    if (blockIdx.x == 0 && threadIdx.x == 0) g_scale[slot] = s;
    float inv = 1.0f / (s + 1e-5f);
    int stride = gridDim.x * blockDim.x;
    for (int i = blockIdx.x * blockDim.x + threadIdx.x; i < F_DIM * F_DIM; i += stride) {
        float qv = rintf(fminf(fmaxf(w[i] * inv, -1.f), 1.f));
        kq[i] = __float2bfloat16(qv);
    }
}

__global__ void split_weight(const float* __restrict__ w, __nv_bfloat16* __restrict__ hi,
                             __nv_bfloat16* __restrict__ lo, int n) {
    int stride = gridDim.x * blockDim.x;
    for (int i = blockIdx.x * blockDim.x + threadIdx.x; i < n; i += stride) {
        float v = w[i];
        __nv_bfloat16 h = __float2bfloat16(v);
        hi[i] = h;
        lo[i] = __float2bfloat16(v - __bfloat162float(h));
    }
}

__global__ void build_combined(const float* zb, const float* za, const float* ze,
                               const float* zm, const float* zs,
                               __nv_bfloat16* __restrict__ ch, __nv_bfloat16* __restrict__ cl) {
    int idx = blockIdx.x * 256 + threadIdx.x;
    int r = idx >> 9;
    int c4 = (idx & 511) * 4;
    const float* src; int off;
    if      (c4 < DB)                { src = zb; off = r * DB + c4; }
    else if (c4 < DB + DA)           { src = za; off = r * DA + (c4 - DB); }
    else if (c4 < DB + DA + DE)      { src = ze; off = r * DE + (c4 - DB - DA); }
    else if (c4 < DB + DA + DE + DM) { src = zm; off = r * DM + (c4 - DB - DA - DE); }
    else                             { src = zs; off = r * DS + (c4 - DB - DA - DE - DM); }
    float4 v = *reinterpret_cast<const float4*>(src + off);
    float vv[4] = {v.x, v.y, v.z, v.w};
    __nv_bfloat16 h[4], l[4];
#pragma unroll
    for (int j = 0; j < 4; j++) {
        h[j] = __float2bfloat16(vv[j]);
        l[j] = __float2bfloat16(vv[j] - __bfloat162float(h[j]));
    }
    size_t o = (size_t)r * F_DIM + c4;
    uint2 uh; uh.x = pack2(h[0], h[1]); uh.y = pack2(h[2], h[3]);
    uint2 ul; ul.x = pack2(l[0], l[1]); ul.y = pack2(l[2], l[3]);
    *reinterpret_cast<uint2*>(&ch[o]) = uh;
    *reinterpret_cast<uint2*>(&cl[o]) = ul;
}

__global__ void fused_sig_ln(const float* __restrict__ g, const float* __restrict__ t,
                             const float* __restrict__ lg, const float* __restrict__ lb,
                             float* __restrict__ fused,
                             __nv_bfloat16* __restrict__ fh, __nv_bfloat16* __restrict__ fl) {
    int row = blockIdx.x;
    size_t base = (size_t)row * F_DIM;
    float v[8], s1 = 0.f, s2 = 0.f;
#pragma unroll
    for (int i = 0; i < 8; i++) {
        int c = i * 256 + threadIdx.x;
        float gg = g[base + c], tt = t[base + c];
        float f = tt / (1.0f + expf(-1.2f * gg));
        v[i] = f; s1 += f; s2 += f * f;
    }
    __shared__ float rs[8], rq[8];
    int wd = threadIdx.x >> 5, ln = threadIdx.x & 31;
    float a = warpSum(s1), b = warpSum(s2);
    if (ln == 0) { rs[wd] = a; rq[wd] = b; }
    __syncthreads();
    if (wd == 0) {
        float x = (ln < 8) ? rs[ln] : 0.f;
        float y = (ln < 8) ? rq[ln] : 0.f;
        x = warpSum(x); y = warpSum(y);
        if (ln == 0) { rs[0] = x; rq[0] = y; }
    }
    __syncthreads();
    float mean = rs[0] * (1.0f / F_DIM);
    float var = rq[0] * (1.0f / F_DIM) - mean * mean;
    float inv = rsqrtf(var + 1e-5f);
#pragma unroll
    for (int i = 0; i < 8; i++) {
        int c = i * 256 + threadIdx.x;
        float y = (v[i] - mean) * inv * lg[c] + lb[c];
        fused[base + c] = y;
        __nv_bfloat16 h = __float2bfloat16(y);
        fh[base + c] = h;
        fl[base + c] = __float2bfloat16(y - __bfloat162float(h));
    }
}

__global__ void final_ln(const float* __restrict__ fused, const float* __restrict__ mlp,
                         const float* __restrict__ lg, const float* __restrict__ lb,
                         float* __restrict__ out) {
    int row = blockIdx.x;
    size_t base = (size_t)row * F_DIM;
    float v[8], s1 = 0.f, s2 = 0.f;
#pragma unroll
    for (int i = 0; i < 8; i++) {
        int c = i * 256 + threadIdx.x;
        float f = fused[base + c] + mlp[base + c];
        v[i] = f; s1 += f; s2 += f * f;
    }
    __shared__ float rs[8], rq[8];
    int wd = threadIdx.x >> 5, ln = threadIdx.x & 31;
    float a = warpSum(s1), b = warpSum(s2);
    if (ln == 0) { rs[wd] = a; rq[wd] = b; }
    __syncthreads();
    if (wd == 0) {
        float x = (ln < 8) ? rs[ln] : 0.f;
        float y = (ln < 8) ? rq[ln] : 0.f;
        x = warpSum(x); y = warpSum(y);
        if (ln == 0) { rs[0] = x; rq[0] = y; }
    }
    __syncthreads();
    float mean = rs[0] * (1.0f / F_DIM);
    float var = rq[0] * (1.0f / F_DIM) - mean * mean;
    float inv = rsqrtf(var + 1e-5f);
#pragma unroll
    for (int i = 0; i < 8; i++) {
        int c = i * 256 + threadIdx.x;
        out[base + c] = (v[i] - mean) * inv * lg[c] + lb[c];
    }
}

// ---- launch ----
extern "C" void kernel_launch(void* const* d_in, const int* in_sizes, int n_in,
                              void* d_out, int out_size) {
    (void)in_sizes; (void)n_in; (void)out_size;
    const float* zb = (const float*)d_in[0];
    const float* za = (const float*)d_in[1];
    const float* ze = (const float*)d_in[2];
    const float* zm = (const float*)d_in[3];
    const float* zs = (const float*)d_in[4];
    const float* gate_w1 = (const float*)d_in[5];
    const float* gate_b1 = (const float*)d_in[6];
    const float* gate_w2 = (const float*)d_in[7];
    const float* gate_b2 = (const float*)d_in[8];
    const float* tr_w1 = (const float*)d_in[9];
    const float* tr_b1 = (const float*)d_in[10];
    const float* tr_w2 = (const float*)d_in[11];
    const float* tr_b2 = (const float*)d_in[12];
    const float* mlp_w1 = (const float*)d_in[13];
    const float* mlp_b1 = (const float*)d_in[14];
    const float* mlp_w2 = (const float*)d_in[15];
    const float* mlp_b2 = (const float*)d_in[16];
    const float* ln1_g = (const float*)d_in[17];
    const float* ln1_b = (const float*)d_in[18];
    const float* ln2_g = (const float*)d_in[19];
    const float* ln2_b = (const float*)d_in[20];
    float* out = (float*)d_out;

    __nv_bfloat16 *ch, *cl, *ah, *al, *wkb, *w1h, *w1l, *w2h, *w2l;
    float *fa, *fb, *fu, *scb;
    cudaGetSymbolAddress((void**)&ch,  g_comb_hi);
    cudaGetSymbolAddress((void**)&cl,  g_comb_lo);
    cudaGetSymbolAddress((void**)&ah,  g_act_hi);
    cudaGetSymbolAddress((void**)&al,  g_act_lo);
    cudaGetSymbolAddress((void**)&wkb, g_wk);
    cudaGetSymbolAddress((void**)&w1h, g_w1h);
    cudaGetSymbolAddress((void**)&w1l, g_w1l);
    cudaGetSymbolAddress((void**)&w2h, g_w2h);
    cudaGetSymbolAddress((void**)&w2l, g_w2l);
    cudaGetSymbolAddress((void**)&fa,  g_f32a);
    cudaGetSymbolAddress((void**)&fb,  g_f32b);
    cudaGetSymbolAddress((void**)&fu,  g_fused);
    cudaGetSymbolAddress((void**)&scb, g_scale);
    __nv_bfloat16* wk0 = wkb;
    __nv_bfloat16* wk1 = wkb + (size_t)F_DIM * F_DIM;
    __nv_bfloat16* wk2 = wkb + 2 * (size_t)F_DIM * F_DIM;
    __nv_bfloat16* wk3 = wkb + 3 * (size_t)F_DIM * F_DIM;

    cudaFuncSetAttribute(gemm_tc<0>, cudaFuncAttributeMaxDynamicSharedMemorySize, GEMM_SMEM_DYN);
    cudaFuncSetAttribute(gemm_tc<1>, cudaFuncAttributeMaxDynamicSharedMemorySize, GEMM_SMEM_DYN);

    absmean_partial<<<dim3(64, 4), 256>>>(gate_w1, gate_w2, tr_w1, tr_w2);
    quantize_ternary<<<256, 256>>>(gate_w1, wk0, 0);
    quantize_ternary<<<256, 256>>>(gate_w2, wk1, 1);
    quantize_ternary<<<256, 256>>>(tr_w1, wk2, 2);
    quantize_ternary<<<256, 256>>>(tr_w2, wk3, 3);
    split_weight<<<2048, 256>>>(mlp_w1, w1h, w1l, F2_DIM * F_DIM);
    split_weight<<<2048, 256>>>(mlp_w2, w2h, w2l, F_DIM * F2_DIM);
    build_combined<<<(B_ROWS * 512) / 256, 256>>>(zb, za, ze, zm, zs, ch, cl);

    dim3 g2048(F_DIM / TILE_N, B_ROWS / TILE_M);   // (16, 64)
    dim3 g4096(F2_DIM / TILE_N, B_ROWS / TILE_M);  // (32, 64)

    // gate path
    gemm_tc<0><<<g2048, 256, GEMM_SMEM_DYN>>>(ch, cl, nullptr, wk0, wk0, nullptr,
        2, F_DIM, F_DIM, scb + 0, gate_b1, nullptr, ah, al);
    gemm_tc<1><<<g2048, 256, GEMM_SMEM_DYN>>>(ah, al, nullptr, wk1, wk1, nullptr,
        2, F_DIM, F_DIM, scb + 1, gate_b2, fa, nullptr, nullptr);
    // transform path
    gemm_tc<0><<<g2048, 256, GEMM_SMEM_DYN>>>(ch, cl, nullptr, wk2, wk2, nullptr,
        2, F_DIM, F_DIM, scb + 2, tr_b1, nullptr, ah, al);
    gemm_tc<1><<<g2048, 256, GEMM_SMEM_DYN>>>(ah, al, nullptr, wk3, wk3, nullptr,
        2, F_DIM, F_DIM, scb + 3, tr_b2, fb, nullptr, nullptr);
    // sigmoid-gate fuse + ln1 (writes fused fp32 + bf16 hi/lo into comb buffers)
    fused_sig_ln<<<B_ROWS, 256>>>(fa, fb, ln1_g, ln1_b, fu, ch, cl);
    // mlp (3-term bf16 split: xh*wh + xh*wl + xl*wh)
    gemm_tc<0><<<g4096, 256, GEMM_SMEM_DYN>>>(ch, ch, cl, w1h, w1l, w1h,
        3, F2_DIM, F_DIM, nullptr, mlp_b1, nullptr, ah, al);
    gemm_tc<1><<<g2048, 256, GEMM_SMEM_DYN>>>(ah, ah, al, w2h, w2l, w2h,
        3, F_DIM, F2_DIM, nullptr, mlp_b2, fa, nullptr, nullptr);
    // residual + ln2
    final_ln<<<B_ROWS, 256>>>(fu, fa, ln2_g, ln2_b, out);
}